// round 12
// baseline (speedup 1.0000x reference)
#include <cuda_runtime.h>
#include <cuda_fp16.h>
#include <cstdint>

#define NN 50000
#define NE 800000

// ---------------- scratch (static device globals; no allocation) ----------------
__device__ int   g_deg_out[NN];
__device__ int   g_deg_in[NN];
__device__ float g_ns[NN];
__device__ float g_nd[NN];
__device__ int   g_rowptr[NN + 1];
__device__ int   g_cursor[NN];
__device__ int   g_csrc[NE];
__device__ int   g_is64;

// fragment-packed f16 A operands:
// uint2 element (r, ks, q) = { f16pair(cols ks*16+2q, +1), f16pair(cols ks*16+2q+8, +9) }
// linear index (r*16 + ks)*4 + q
__device__ uint2 g_A1p[(size_t)NN * 64];    // layer1 A = x * ns        (f16)
__device__ uint2 g_A2p[(size_t)NN * 64];    // layer2 A = relu(conv1)*ns (f16)

// f16 feature stores for aggregation gathers
__device__ uint4 g_H1h[(size_t)NN * 32];    // H1  [NN,256] f16
__device__ uint2 g_H2h[(size_t)NN * 32];    // H2p [NN,128] f16

// weight fragment packs (f16 hi/lo, two-term): uint2{hi_pair, lo_pair},
// index ((ks*NT8 + nt8)*2 + breg)*32 + lane
__device__ uint2 g_B1p[16 * 32 * 2 * 32];   // W1: Nt=256
__device__ uint2 g_B2p[16 * 16 * 2 * 32];   // W2: Nt=128

#define W1P (16 * 32 * 2 * 32)              // 32768
#define W2P (16 * 16 * 2 * 32)              // 16384

// ---------------- small helpers ----------------
__device__ __forceinline__ uint32_t h2u(__half2 h) {
    return *reinterpret_cast<uint32_t*>(&h);
}
__device__ __forceinline__ float2 u2f2(uint32_t u) {
    __half2 h = *reinterpret_cast<__half2*>(&u);
    return __half22float2(h);
}
__device__ __forceinline__ uint32_t packh(float f0, float f1) {
    return h2u(__floats2half2_rn(f0, f1));
}
// f16 hi/lo split of two fp32: {hi_pair, lo_pair}
__device__ __forceinline__ uint2 split_pack_h(float f0, float f1) {
    __half h0 = __float2half_rn(f0), h1 = __float2half_rn(f1);
    __half l0 = __float2half_rn(f0 - __half2float(h0));
    __half l1 = __float2half_rn(f1 - __half2float(h1));
    uint2 r;
    r.x = (uint32_t)__half_as_ushort(h0) | ((uint32_t)__half_as_ushort(h1) << 16);
    r.y = (uint32_t)__half_as_ushort(l0) | ((uint32_t)__half_as_ushort(l1) << 16);
    return r;
}

__device__ __forceinline__ void mma_f16(float* c, const uint32_t* a, uint32_t b0, uint32_t b1) {
    asm volatile(
        "mma.sync.aligned.m16n8k16.row.col.f32.f16.f16.f32 "
        "{%0,%1,%2,%3}, {%4,%5,%6,%7}, {%8,%9}, {%0,%1,%2,%3};"
        : "+f"(c[0]), "+f"(c[1]), "+f"(c[2]), "+f"(c[3])
        : "r"(a[0]), "r"(a[1]), "r"(a[2]), "r"(a[3]), "r"(b0), "r"(b1));
}

// ---------------- edge index accessor (dtype-robust) ----------------
__device__ __forceinline__ int edge_at(const void* p, int i, int is64) {
    if (is64) return (int)((const long long*)p)[i];
    return ((const int*)p)[i];
}

// ---------------- fused init: zero counters + dtype detect ----------------
__global__ void k_init(const int* __restrict__ src_as_i32) {
    int i = blockIdx.x * 256 + threadIdx.x;
    if (i < NN) { g_deg_out[i] = 0; g_deg_in[i] = 0; g_cursor[i] = 0; }
    if (blockIdx.x == 0 && threadIdx.x == 0) {
        int allzero = 1;
        for (int j = 0; j < 256; j++)
            if (src_as_i32[2 * j + 1] != 0) { allzero = 0; break; }
        g_is64 = allzero;
    }
}

__global__ void k_degree(const void* __restrict__ src, const void* __restrict__ dst) {
    int e = blockIdx.x * 256 + threadIdx.x;
    if (e < NE) {
        int is64 = g_is64;
        unsigned s = (unsigned)edge_at(src, e, is64);
        unsigned d = (unsigned)edge_at(dst, e, is64);
        if (s < NN) atomicAdd(&g_deg_out[s], 1);
        if (d < NN) atomicAdd(&g_deg_in[d], 1);
    }
}

// ---------------- fused norm + exclusive scan (single block) ----------------
__global__ void k_normscan() {
    __shared__ int sh[1024];
    const int CH = (NN + 1023) / 1024;
    int tid = threadIdx.x;
    int st = tid * CH;
    int en = st + CH; if (en > NN) en = NN;
    int s = 0;
    for (int j = st; j < en; ++j) {
        int a = g_deg_out[j]; if (a < 1) a = 1;
        int b = g_deg_in[j];
        g_ns[j] = rsqrtf((float)a);
        g_nd[j] = rsqrtf((float)(b < 1 ? 1 : b));
        s += b;
    }
    sh[tid] = s;
    __syncthreads();
    for (int off = 1; off < 1024; off <<= 1) {
        int v = 0;
        if (tid >= off) v = sh[tid - off];
        __syncthreads();
        sh[tid] += v;
        __syncthreads();
    }
    int run = sh[tid] - s;
    for (int j = st; j < en; ++j) { g_rowptr[j] = run; run += g_deg_in[j]; }
    if (tid == 1023) g_rowptr[NN] = sh[1023];
}

__global__ void k_csr(const void* __restrict__ src, const void* __restrict__ dst) {
    int e = blockIdx.x * 256 + threadIdx.x;
    if (e < NE) {
        int is64 = g_is64;
        unsigned s = (unsigned)edge_at(src, e, is64);
        unsigned d = (unsigned)edge_at(dst, e, is64);
        if (s < NN && d < NN) {
            int pos = atomicAdd(&g_cursor[d], 1);
            int slot = g_rowptr[d] + pos;
            if (slot < NE) g_csrc[slot] = (int)s;
        }
    }
}

// ---------------- fused pack: W1, W2 (two-term hi/lo) and x -> f16 fragments ------
// W fragment math identical to R10's k_wpack; A part identical to R10's k_apack.
__global__ void k_pack(const float* __restrict__ x,
                       const float* __restrict__ W1,
                       const float* __restrict__ W2) {
    int idx = blockIdx.x * 256 + threadIdx.x;
    if (idx < W1P + W2P) {
        const float* W = (idx < W1P) ? W1 : W2;
        uint2* out = (idx < W1P) ? g_B1p : g_B2p;
        int i = (idx < W1P) ? idx : idx - W1P;
        int Nt = (idx < W1P) ? 256 : 128;
        int NT8 = Nt >> 3;
        int lane = i & 31;
        int breg = (i >> 5) & 1;
        int rest = i >> 6;                // ks*NT8 + nt8
        int nt8 = rest % NT8;
        int ks = rest / NT8;
        int k = ks * 16 + (lane & 3) * 2 + breg * 8;
        int n = nt8 * 8 + (lane >> 2);
        float w0 = W[(size_t)k * Nt + n];
        float w1 = W[(size_t)(k + 1) * Nt + n];
        out[i] = split_pack_h(w0, w1);
    } else {
        int i = idx - (W1P + W2P);
        if (i >= NN * 64) return;
        int r = i >> 6;
        int ks = (i >> 2) & 15;
        int q = i & 3;
        const float* ap = x + (size_t)r * 256 + ks * 16 + q * 2;
        float s = g_ns[r];
        float2 v0 = *(const float2*)ap;
        float2 v1 = *(const float2*)(ap + 8);
        uint2 o;
        o.x = packh(v0.x * s, v0.y * s);
        o.y = packh(v1.x * s, v1.y * s);
        g_A1p[i] = o;
    }
}

// ---------------- MMA GEMM: H[128 x Nt] (f16 out) = Apack @ (Wh + Wl) -----------
// R10 configuration restored: 2 MMAs per (mt,j) per kstep (latency hiding).
template <bool L1>
__global__ void __launch_bounds__(256) k_mma() {
    constexpr int Nt = L1 ? 256 : 128;
    constexpr int NT8 = Nt >> 3;
    const uint2* Ap = L1 ? g_A1p : g_A2p;
    uint32_t* Ch = L1 ? (uint32_t*)g_H1h : (uint32_t*)g_H2h;
    const uint2* Bp = L1 ? g_B1p : g_B2p;

    int tid = threadIdx.x;
    int wid = tid >> 5, lid = tid & 31;
    int wm = wid >> 1, wn = wid & 1;
    int g = lid >> 2, q = lid & 3;
    int brow = blockIdx.x * 128;
    int bcol = blockIdx.y * 128;

    int rbase = brow + wm * 32 + g;
    int rows[4] = {rbase, rbase + 8, rbase + 16, rbase + 24};
    bool valid[4];
#pragma unroll
    for (int i = 0; i < 4; i++) valid[i] = rows[i] < NN;

    float acc[2][8][4];
#pragma unroll
    for (int mt = 0; mt < 2; mt++)
#pragma unroll
        for (int j = 0; j < 8; j++)
#pragma unroll
            for (int c = 0; c < 4; c++) acc[mt][j][c] = 0.f;

    const uint2* bbase = Bp + (size_t)((bcol >> 3) + wn * 8) * 64 + lid;

    for (int ks = 0; ks < 16; ks++) {
        // ---- A fragments: one 8B load per row per kstep ----
        uint32_t a[2][4];
#pragma unroll
        for (int ri = 0; ri < 4; ri++) {
            uint2 v = make_uint2(0u, 0u);
            if (valid[ri]) v = Ap[((size_t)rows[ri] * 16 + ks) * 4 + q];
            int mt = ri >> 1, half = ri & 1;
            a[mt][half] = v.x;
            a[mt][half + 2] = v.y;
        }
        // ---- B fragments (pre-packed hi/lo) ----
        const uint2* bk = bbase + (size_t)ks * NT8 * 64;
        uint2 b0[8], b1[8];
#pragma unroll
        for (int j = 0; j < 8; j++) {
            b0[j] = bk[j * 64];
            b1[j] = bk[j * 64 + 32];
        }
        // ---- MMAs: A@Wh + A@Wl ----
#pragma unroll
        for (int mt = 0; mt < 2; mt++)
#pragma unroll
            for (int j = 0; j < 8; j++) {
                mma_f16(acc[mt][j], a[mt], b0[j].x, b1[j].x);
                mma_f16(acc[mt][j], a[mt], b0[j].y, b1[j].y);
            }
    }

    // ---- epilogue: write f16 pairs ----
    int cb = bcol + wn * 64 + q * 2;
#pragma unroll
    for (int mt = 0; mt < 2; mt++) {
        int r0 = rows[mt * 2], r1 = rows[mt * 2 + 1];
#pragma unroll
        for (int j = 0; j < 8; j++) {
            int ci = (cb + j * 8) >> 1;
            if (valid[mt * 2])
                Ch[(size_t)r0 * (Nt / 2) + ci] = packh(acc[mt][j][0], acc[mt][j][1]);
            if (valid[mt * 2 + 1])
                Ch[(size_t)r1 * (Nt / 2) + ci] = packh(acc[mt][j][2], acc[mt][j][3]);
        }
    }
}

// ---------------- aggregation layer 1 (f16 gather, fp32 accum) ----------------
// emits layer-2 A directly in fragment-packed f16 form.
__global__ void k_agg1(const float* __restrict__ b1) {
    int node = blockIdx.x * 8 + threadIdx.y;
    if (node >= NN) return;
    int f = threadIdx.x;  // 0..31, cols 8f..8f+7
    int beg = g_rowptr[node], end = g_rowptr[node + 1];

    float acc[8];
#pragma unroll
    for (int i = 0; i < 8; i++) acc[i] = 0.f;

    int e = beg;
    for (; e + 4 <= end; e += 4) {
        uint4 v0 = g_H1h[(size_t)g_csrc[e] * 32 + f];
        uint4 v1 = g_H1h[(size_t)g_csrc[e + 1] * 32 + f];
        uint4 v2 = g_H1h[(size_t)g_csrc[e + 2] * 32 + f];
        uint4 v3 = g_H1h[(size_t)g_csrc[e + 3] * 32 + f];
#pragma unroll
        for (int w = 0; w < 4; w++) {
            uint32_t uu[4] = {v0.x, v0.y, v0.z, v0.w};
            uint32_t vv[4] = {v1.x, v1.y, v1.z, v1.w};
            uint32_t ww[4] = {v2.x, v2.y, v2.z, v2.w};
            uint32_t zz[4] = {v3.x, v3.y, v3.z, v3.w};
            float2 t0 = u2f2(uu[w]), t1 = u2f2(vv[w]), t2 = u2f2(ww[w]), t3 = u2f2(zz[w]);
            acc[2 * w] += (t0.x + t1.x) + (t2.x + t3.x);
            acc[2 * w + 1] += (t0.y + t1.y) + (t2.y + t3.y);
        }
    }
    for (; e < end; e++) {
        uint4 v = g_H1h[(size_t)g_csrc[e] * 32 + f];
        uint32_t uu[4] = {v.x, v.y, v.z, v.w};
#pragma unroll
        for (int w = 0; w < 4; w++) {
            float2 t = u2f2(uu[w]);
            acc[2 * w] += t.x;
            acc[2 * w + 1] += t.y;
        }
    }

    float nd = g_nd[node], ns = g_ns[node];
    float4 bb0 = ((const float4*)b1)[2 * f];
    float4 bb1 = ((const float4*)b1)[2 * f + 1];
    float bias[8] = {bb0.x, bb0.y, bb0.z, bb0.w, bb1.x, bb1.y, bb1.z, bb1.w};
    float r[8];
#pragma unroll
    for (int i = 0; i < 8; i++)
        r[i] = fmaxf(fmaf(acc[i], nd, bias[i]), 0.f) * ns;

    // packed write: pair i covers cols (8f+2i, 8f+2i+1); ks = f>>1, q = i, slot = f&1
    uint32_t* o = (uint32_t*)g_A2p;
    size_t base = (((size_t)node * 16 + (f >> 1)) * 4) * 2 + (f & 1);
#pragma unroll
    for (int i = 0; i < 4; i++)
        o[base + i * 2] = packh(r[2 * i], r[2 * i + 1]);
}

// ---------------- aggregation layer 2 (f16 gather, fp32 out) ----------------
__global__ void k_agg2(const float* __restrict__ b2, float* __restrict__ out) {
    int node = blockIdx.x * 8 + threadIdx.y;
    if (node >= NN) return;
    int f = threadIdx.x;  // 0..31, cols 4f..4f+3
    int beg = g_rowptr[node], end = g_rowptr[node + 1];

    float acc[4];
#pragma unroll
    for (int i = 0; i < 4; i++) acc[i] = 0.f;

    int e = beg;
    for (; e + 4 <= end; e += 4) {
        uint2 v0 = g_H2h[(size_t)g_csrc[e] * 32 + f];
        uint2 v1 = g_H2h[(size_t)g_csrc[e + 1] * 32 + f];
        uint2 v2 = g_H2h[(size_t)g_csrc[e + 2] * 32 + f];
        uint2 v3 = g_H2h[(size_t)g_csrc[e + 3] * 32 + f];
        float2 t0 = u2f2(v0.x), t1 = u2f2(v1.x), t2 = u2f2(v2.x), t3 = u2f2(v3.x);
        acc[0] += (t0.x + t1.x) + (t2.x + t3.x);
        acc[1] += (t0.y + t1.y) + (t2.y + t3.y);
        t0 = u2f2(v0.y); t1 = u2f2(v1.y); t2 = u2f2(v2.y); t3 = u2f2(v3.y);
        acc[2] += (t0.x + t1.x) + (t2.x + t3.x);
        acc[3] += (t0.y + t1.y) + (t2.y + t3.y);
    }
    for (; e < end; e++) {
        uint2 v = g_H2h[(size_t)g_csrc[e] * 32 + f];
        float2 t = u2f2(v.x);
        acc[0] += t.x; acc[1] += t.y;
        t = u2f2(v.y);
        acc[2] += t.x; acc[3] += t.y;
    }

    float nd = g_nd[node];
    float4 bb = ((const float4*)b2)[f];
    float4 r;
    r.x = fmaf(acc[0], nd, bb.x);
    r.y = fmaf(acc[1], nd, bb.y);
    r.z = fmaf(acc[2], nd, bb.z);
    r.w = fmaf(acc[3], nd, bb.w);
    ((float4*)out)[(size_t)node * 32 + f] = r;
}

// ---------------- launch ----------------
extern "C" void kernel_launch(void* const* d_in, const int* in_sizes, int n_in,
                              void* d_out, int out_size) {
    const float* x   = (const float*)d_in[0];
    const void*  src = d_in[1];
    const void*  dst = d_in[2];
    const float* W1  = (const float*)d_in[3];
    const float* b1  = (const float*)d_in[4];
    const float* W2  = (const float*)d_in[5];
    const float* b2  = (const float*)d_in[6];
    float* out = (float*)d_out;

    k_init<<<(NN + 255) / 256, 256>>>((const int*)src);
    k_degree<<<(NE + 255) / 256, 256>>>(src, dst);
    k_normscan<<<1, 1024>>>();
    k_csr<<<(NE + 255) / 256, 256>>>(src, dst);
    k_pack<<<(W1P + W2P + NN * 64 + 255) / 256, 256>>>(x, W1, W2);

    const int GB = (NN + 127) / 128;  // 391
    k_mma<true><<<dim3(GB, 2), 256>>>();
    k_agg1<<<(NN + 7) / 8, dim3(32, 8)>>>(b1);
    k_mma<false><<<dim3(GB, 1), 256>>>();
    k_agg2<<<(NN + 7) / 8, dim3(32, 8)>>>(b2, out);
}

// round 13
// speedup vs baseline: 1.7047x; 1.7047x over previous
#include <cuda_runtime.h>
#include <cuda_fp16.h>
#include <cstdint>

#define NN 50000
#define NE 800000

// ---------------- scratch (static device globals; no allocation) ----------------
__device__ int   g_deg_out[NN];
__device__ int   g_deg_in[NN];
__device__ float g_ns[NN];
__device__ float g_nd[NN];
__device__ int   g_rowptr[NN + 1];
__device__ int   g_cursor[NN];
__device__ int   g_csrc[NE];
__device__ int   g_is64;

// fragment-packed f16 A operands:
// uint2 element (r, ks, q) = { f16pair(cols ks*16+2q, +1), f16pair(cols ks*16+2q+8, +9) }
// linear index (r*16 + ks)*4 + q
__device__ uint2 g_A1p[(size_t)NN * 64];    // layer1 A = x * ns        (f16)
__device__ uint2 g_A2p[(size_t)NN * 64];    // layer2 A = relu(conv1)*ns (f16)

// f16 feature stores for aggregation gathers
__device__ uint4 g_H1h[(size_t)NN * 32];    // H1  [NN,256] f16
__device__ uint2 g_H2h[(size_t)NN * 32];    // H2p [NN,128] f16

// weight fragment packs (single-term f16): uint2{b0_pair, b1_pair},
// index (ks*NT8 + nt8)*32 + lane
__device__ uint2 g_B1p[16 * 32 * 32];       // W1: Nt=256
__device__ uint2 g_B2p[16 * 16 * 32];       // W2: Nt=128

#define W1P (16 * 32 * 32)                  // 16384
#define W2P (16 * 16 * 32)                  // 8192

// ---------------- small helpers ----------------
__device__ __forceinline__ uint32_t h2u(__half2 h) {
    return *reinterpret_cast<uint32_t*>(&h);
}
__device__ __forceinline__ float2 u2f2(uint32_t u) {
    __half2 h = *reinterpret_cast<__half2*>(&u);
    return __half22float2(h);
}
__device__ __forceinline__ uint32_t packh(float f0, float f1) {
    return h2u(__floats2half2_rn(f0, f1));
}

__device__ __forceinline__ void mma_f16(float* c, const uint32_t* a, uint32_t b0, uint32_t b1) {
    asm volatile(
        "mma.sync.aligned.m16n8k16.row.col.f32.f16.f16.f32 "
        "{%0,%1,%2,%3}, {%4,%5,%6,%7}, {%8,%9}, {%0,%1,%2,%3};"
        : "+f"(c[0]), "+f"(c[1]), "+f"(c[2]), "+f"(c[3])
        : "r"(a[0]), "r"(a[1]), "r"(a[2]), "r"(a[3]), "r"(b0), "r"(b1));
}

// ---------------- edge index accessor (dtype-robust) ----------------
__device__ __forceinline__ int edge_at(const void* p, int i, int is64) {
    if (is64) return (int)((const long long*)p)[i];
    return ((const int*)p)[i];
}

// ---------------- fused init: zero counters + dtype detect ----------------
__global__ void k_init(const int* __restrict__ src_as_i32) {
    int i = blockIdx.x * 256 + threadIdx.x;
    if (i < NN) { g_deg_out[i] = 0; g_deg_in[i] = 0; g_cursor[i] = 0; }
    if (blockIdx.x == 0 && threadIdx.x == 0) {
        int allzero = 1;
        for (int j = 0; j < 256; j++)
            if (src_as_i32[2 * j + 1] != 0) { allzero = 0; break; }
        g_is64 = allzero;
    }
}

__global__ void k_degree(const void* __restrict__ src, const void* __restrict__ dst) {
    int e = blockIdx.x * 256 + threadIdx.x;
    if (e < NE) {
        int is64 = g_is64;
        unsigned s = (unsigned)edge_at(src, e, is64);
        unsigned d = (unsigned)edge_at(dst, e, is64);
        if (s < NN) atomicAdd(&g_deg_out[s], 1);
        if (d < NN) atomicAdd(&g_deg_in[d], 1);
    }
}

// ---------------- norm: WIDE kernel (rsqrt spread over the chip) ----------------
__global__ void k_norm() {
    int i = blockIdx.x * 256 + threadIdx.x;
    if (i < NN) {
        int a = g_deg_out[i]; if (a < 1) a = 1;
        int b = g_deg_in[i];  if (b < 1) b = 1;
        g_ns[i] = rsqrtf((float)a);
        g_nd[i] = rsqrtf((float)b);
    }
}

// ---------------- exclusive scan (single block, INT ONLY — no MUFU) -------------
__global__ void k_scan() {
    __shared__ int sh[1024];
    const int CH = (NN + 1023) / 1024;
    int tid = threadIdx.x;
    int st = tid * CH;
    int en = st + CH; if (en > NN) en = NN;
    int s = 0;
    for (int j = st; j < en; ++j) s += g_deg_in[j];
    sh[tid] = s;
    __syncthreads();
    for (int off = 1; off < 1024; off <<= 1) {
        int v = 0;
        if (tid >= off) v = sh[tid - off];
        __syncthreads();
        sh[tid] += v;
        __syncthreads();
    }
    int run = sh[tid] - s;
    for (int j = st; j < en; ++j) { g_rowptr[j] = run; run += g_deg_in[j]; }
    if (tid == 1023) g_rowptr[NN] = sh[1023];
}

__global__ void k_csr(const void* __restrict__ src, const void* __restrict__ dst) {
    int e = blockIdx.x * 256 + threadIdx.x;
    if (e < NE) {
        int is64 = g_is64;
        unsigned s = (unsigned)edge_at(src, e, is64);
        unsigned d = (unsigned)edge_at(dst, e, is64);
        if (s < NN && d < NN) {
            int pos = atomicAdd(&g_cursor[d], 1);
            int slot = g_rowptr[d] + pos;
            if (slot < NE) g_csrc[slot] = (int)s;
        }
    }
}

// ---------------- fused pack: W1, W2 (single-term f16) and x -> f16 fragments ----
// b0: k = ks*16 + (lane&3)*2 (+1); b1: k += 8. n = nt8*8 + lane>>2.
__global__ void k_pack(const float* __restrict__ x,
                       const float* __restrict__ W1,
                       const float* __restrict__ W2) {
    int idx = blockIdx.x * 256 + threadIdx.x;
    if (idx < W1P + W2P) {
        const float* W = (idx < W1P) ? W1 : W2;
        uint2* out = (idx < W1P) ? g_B1p : g_B2p;
        int i = (idx < W1P) ? idx : idx - W1P;
        int Nt = (idx < W1P) ? 256 : 128;
        int NT8 = Nt >> 3;
        int lane = i & 31;
        int rest = i >> 5;               // ks*NT8 + nt8
        int nt8 = rest % NT8;
        int ks = rest / NT8;
        int k = ks * 16 + (lane & 3) * 2;
        int n = nt8 * 8 + (lane >> 2);
        uint2 o;
        o.x = packh(W[(size_t)k * Nt + n], W[(size_t)(k + 1) * Nt + n]);
        o.y = packh(W[(size_t)(k + 8) * Nt + n], W[(size_t)(k + 9) * Nt + n]);
        out[i] = o;
    } else {
        int i = idx - (W1P + W2P);
        if (i >= NN * 64) return;
        int r = i >> 6;
        int ks = (i >> 2) & 15;
        int q = i & 3;
        const float* ap = x + (size_t)r * 256 + ks * 16 + q * 2;
        float s = g_ns[r];
        float2 v0 = *(const float2*)ap;
        float2 v1 = *(const float2*)(ap + 8);
        uint2 o;
        o.x = packh(v0.x * s, v0.y * s);
        o.y = packh(v1.x * s, v1.y * s);
        g_A1p[i] = o;
    }
}

// ---------------- MMA GEMM: H[128 x Nt] (f16 out) = Apack @ Wf16 ----------------
// single-term weights: 1 MMA per (mt,j) per kstep (R11 config, −59us vs two-term).
template <bool L1>
__global__ void __launch_bounds__(256) k_mma() {
    constexpr int Nt = L1 ? 256 : 128;
    constexpr int NT8 = Nt >> 3;
    const uint2* Ap = L1 ? g_A1p : g_A2p;
    uint32_t* Ch = L1 ? (uint32_t*)g_H1h : (uint32_t*)g_H2h;
    const uint2* Bp = L1 ? g_B1p : g_B2p;

    int tid = threadIdx.x;
    int wid = tid >> 5, lid = tid & 31;
    int wm = wid >> 1, wn = wid & 1;
    int g = lid >> 2, q = lid & 3;
    int brow = blockIdx.x * 128;
    int bcol = blockIdx.y * 128;

    int rbase = brow + wm * 32 + g;
    int rows[4] = {rbase, rbase + 8, rbase + 16, rbase + 24};
    bool valid[4];
#pragma unroll
    for (int i = 0; i < 4; i++) valid[i] = rows[i] < NN;

    float acc[2][8][4];
#pragma unroll
    for (int mt = 0; mt < 2; mt++)
#pragma unroll
        for (int j = 0; j < 8; j++)
#pragma unroll
            for (int c = 0; c < 4; c++) acc[mt][j][c] = 0.f;

    const uint2* bbase = Bp + (size_t)((bcol >> 3) + wn * 8) * 32 + lid;

    for (int ks = 0; ks < 16; ks++) {
        // ---- A fragments: one 8B load per row per kstep ----
        uint32_t a[2][4];
#pragma unroll
        for (int ri = 0; ri < 4; ri++) {
            uint2 v = make_uint2(0u, 0u);
            if (valid[ri]) v = Ap[((size_t)rows[ri] * 16 + ks) * 4 + q];
            int mt = ri >> 1, half = ri & 1;
            a[mt][half] = v.x;
            a[mt][half + 2] = v.y;
        }
        // ---- B fragments: one 8B load per j ----
        const uint2* bk = bbase + (size_t)ks * NT8 * 32;
        uint2 b[8];
#pragma unroll
        for (int j = 0; j < 8; j++) b[j] = bk[j * 32];
        // ---- MMAs ----
#pragma unroll
        for (int mt = 0; mt < 2; mt++)
#pragma unroll
            for (int j = 0; j < 8; j++)
                mma_f16(acc[mt][j], a[mt], b[j].x, b[j].y);
    }

    // ---- epilogue: write f16 pairs ----
    int cb = bcol + wn * 64 + q * 2;
#pragma unroll
    for (int mt = 0; mt < 2; mt++) {
        int r0 = rows[mt * 2], r1 = rows[mt * 2 + 1];
#pragma unroll
        for (int j = 0; j < 8; j++) {
            int ci = (cb + j * 8) >> 1;
            if (valid[mt * 2])
                Ch[(size_t)r0 * (Nt / 2) + ci] = packh(acc[mt][j][0], acc[mt][j][1]);
            if (valid[mt * 2 + 1])
                Ch[(size_t)r1 * (Nt / 2) + ci] = packh(acc[mt][j][2], acc[mt][j][3]);
        }
    }
}

// ---------------- aggregation layer 1 (f16 gather, fp32 accum) ----------------
// emits layer-2 A directly in fragment-packed f16 form.
__global__ void k_agg1(const float* __restrict__ b1) {
    int node = blockIdx.x * 8 + threadIdx.y;
    if (node >= NN) return;
    int f = threadIdx.x;  // 0..31, cols 8f..8f+7
    int beg = g_rowptr[node], end = g_rowptr[node + 1];

    float acc[8];
#pragma unroll
    for (int i = 0; i < 8; i++) acc[i] = 0.f;

    int e = beg;
    for (; e + 4 <= end; e += 4) {
        uint4 v0 = g_H1h[(size_t)g_csrc[e] * 32 + f];
        uint4 v1 = g_H1h[(size_t)g_csrc[e + 1] * 32 + f];
        uint4 v2 = g_H1h[(size_t)g_csrc[e + 2] * 32 + f];
        uint4 v3 = g_H1h[(size_t)g_csrc[e + 3] * 32 + f];
#pragma unroll
        for (int w = 0; w < 4; w++) {
            uint32_t uu[4] = {v0.x, v0.y, v0.z, v0.w};
            uint32_t vv[4] = {v1.x, v1.y, v1.z, v1.w};
            uint32_t ww[4] = {v2.x, v2.y, v2.z, v2.w};
            uint32_t zz[4] = {v3.x, v3.y, v3.z, v3.w};
            float2 t0 = u2f2(uu[w]), t1 = u2f2(vv[w]), t2 = u2f2(ww[w]), t3 = u2f2(zz[w]);
            acc[2 * w] += (t0.x + t1.x) + (t2.x + t3.x);
            acc[2 * w + 1] += (t0.y + t1.y) + (t2.y + t3.y);
        }
    }
    for (; e < end; e++) {
        uint4 v = g_H1h[(size_t)g_csrc[e] * 32 + f];
        uint32_t uu[4] = {v.x, v.y, v.z, v.w};
#pragma unroll
        for (int w = 0; w < 4; w++) {
            float2 t = u2f2(uu[w]);
            acc[2 * w] += t.x;
            acc[2 * w + 1] += t.y;
        }
    }

    float nd = g_nd[node], ns = g_ns[node];
    float4 bb0 = ((const float4*)b1)[2 * f];
    float4 bb1 = ((const float4*)b1)[2 * f + 1];
    float bias[8] = {bb0.x, bb0.y, bb0.z, bb0.w, bb1.x, bb1.y, bb1.z, bb1.w};
    float r[8];
#pragma unroll
    for (int i = 0; i < 8; i++)
        r[i] = fmaxf(fmaf(acc[i], nd, bias[i]), 0.f) * ns;

    // packed write: pair i covers cols (8f+2i, 8f+2i+1); ks = f>>1, q = i, slot = f&1
    uint32_t* o = (uint32_t*)g_A2p;
    size_t base = (((size_t)node * 16 + (f >> 1)) * 4) * 2 + (f & 1);
#pragma unroll
    for (int i = 0; i < 4; i++)
        o[base + i * 2] = packh(r[2 * i], r[2 * i + 1]);
}

// ---------------- aggregation layer 2 (f16 gather, fp32 out) ----------------
__global__ void k_agg2(const float* __restrict__ b2, float* __restrict__ out) {
    int node = blockIdx.x * 8 + threadIdx.y;
    if (node >= NN) return;
    int f = threadIdx.x;  // 0..31, cols 4f..4f+3
    int beg = g_rowptr[node], end = g_rowptr[node + 1];

    float acc[4];
#pragma unroll
    for (int i = 0; i < 4; i++) acc[i] = 0.f;

    int e = beg;
    for (; e + 4 <= end; e += 4) {
        uint2 v0 = g_H2h[(size_t)g_csrc[e] * 32 + f];
        uint2 v1 = g_H2h[(size_t)g_csrc[e + 1] * 32 + f];
        uint2 v2 = g_H2h[(size_t)g_csrc[e + 2] * 32 + f];
        uint2 v3 = g_H2h[(size_t)g_csrc[e + 3] * 32 + f];
        float2 t0 = u2f2(v0.x), t1 = u2f2(v1.x), t2 = u2f2(v2.x), t3 = u2f2(v3.x);
        acc[0] += (t0.x + t1.x) + (t2.x + t3.x);
        acc[1] += (t0.y + t1.y) + (t2.y + t3.y);
        t0 = u2f2(v0.y); t1 = u2f2(v1.y); t2 = u2f2(v2.y); t3 = u2f2(v3.y);
        acc[2] += (t0.x + t1.x) + (t2.x + t3.x);
        acc[3] += (t0.y + t1.y) + (t2.y + t3.y);
    }
    for (; e < end; e++) {
        uint2 v = g_H2h[(size_t)g_csrc[e] * 32 + f];
        float2 t = u2f2(v.x);
        acc[0] += t.x; acc[1] += t.y;
        t = u2f2(v.y);
        acc[2] += t.x; acc[3] += t.y;
    }

    float nd = g_nd[node];
    float4 bb = ((const float4*)b2)[f];
    float4 r;
    r.x = fmaf(acc[0], nd, bb.x);
    r.y = fmaf(acc[1], nd, bb.y);
    r.z = fmaf(acc[2], nd, bb.z);
    r.w = fmaf(acc[3], nd, bb.w);
    ((float4*)out)[(size_t)node * 32 + f] = r;
}

// ---------------- launch ----------------
extern "C" void kernel_launch(void* const* d_in, const int* in_sizes, int n_in,
                              void* d_out, int out_size) {
    const float* x   = (const float*)d_in[0];
    const void*  src = d_in[1];
    const void*  dst = d_in[2];
    const float* W1  = (const float*)d_in[3];
    const float* b1  = (const float*)d_in[4];
    const float* W2  = (const float*)d_in[5];
    const float* b2  = (const float*)d_in[6];
    float* out = (float*)d_out;

    k_init<<<(NN + 255) / 256, 256>>>((const int*)src);
    k_degree<<<(NE + 255) / 256, 256>>>(src, dst);
    k_norm<<<(NN + 255) / 256, 256>>>();
    k_scan<<<1, 1024>>>();
    k_csr<<<(NE + 255) / 256, 256>>>(src, dst);
    k_pack<<<(W1P + W2P + NN * 64 + 255) / 256, 256>>>(x, W1, W2);

    const int GB = (NN + 127) / 128;  // 391
    k_mma<true><<<dim3(GB, 2), 256>>>();
    k_agg1<<<(NN + 7) / 8, dim3(32, 8)>>>(b1);
    k_mma<false><<<dim3(GB, 1), 256>>>();
    k_agg2<<<(NN + 7) / 8, dim3(32, 8)>>>(b2, out);
}

// round 14
// speedup vs baseline: 2.1022x; 1.2332x over previous
#include <cuda_runtime.h>
#include <cuda_fp16.h>
#include <cstdint>

#define NN 50000
#define NE 800000
#define NSB 49   // scan blocks: ceil(50000/1024)

// ---------------- scratch (static device globals; no allocation) ----------------
__device__ int   g_deg_out[NN];
__device__ int   g_deg_in[NN];
__device__ float g_ns[NN];
__device__ float g_nd[NN];
__device__ int   g_rowptr[NN + 1];
__device__ int   g_cursor[NN];
__device__ int   g_csrc[NE];
__device__ int   g_is64;
__device__ int   g_bsum[NSB];
__device__ int   g_boff[NSB];

// fragment-packed f16 A operands:
// uint2 element (r, ks, q) = { f16pair(cols ks*16+2q, +1), f16pair(cols ks*16+2q+8, +9) }
// linear index (r*16 + ks)*4 + q
__device__ uint2 g_A1p[(size_t)NN * 64];    // layer1 A = x * ns        (f16)
__device__ uint2 g_A2p[(size_t)NN * 64];    // layer2 A = relu(conv1)*ns (f16)

// f16 feature stores for aggregation gathers
__device__ uint4 g_H1h[(size_t)NN * 32];    // H1  [NN,256] f16
__device__ uint2 g_H2h[(size_t)NN * 32];    // H2p [NN,128] f16

// weight fragment packs (single-term f16): uint2{b0_pair, b1_pair},
// index (ks*NT8 + nt8)*32 + lane
__device__ uint2 g_B1p[16 * 32 * 32];       // W1: Nt=256
__device__ uint2 g_B2p[16 * 16 * 32];       // W2: Nt=128

#define W1P (16 * 32 * 32)                  // 16384
#define W2P (16 * 16 * 32)                  // 8192

// ---------------- small helpers ----------------
__device__ __forceinline__ uint32_t h2u(__half2 h) {
    return *reinterpret_cast<uint32_t*>(&h);
}
__device__ __forceinline__ float2 u2f2(uint32_t u) {
    __half2 h = *reinterpret_cast<__half2*>(&u);
    return __half22float2(h);
}
__device__ __forceinline__ uint32_t packh(float f0, float f1) {
    return h2u(__floats2half2_rn(f0, f1));
}

__device__ __forceinline__ void mma_f16(float* c, const uint32_t* a, uint32_t b0, uint32_t b1) {
    asm volatile(
        "mma.sync.aligned.m16n8k16.row.col.f32.f16.f16.f32 "
        "{%0,%1,%2,%3}, {%4,%5,%6,%7}, {%8,%9}, {%0,%1,%2,%3};"
        : "+f"(c[0]), "+f"(c[1]), "+f"(c[2]), "+f"(c[3])
        : "r"(a[0]), "r"(a[1]), "r"(a[2]), "r"(a[3]), "r"(b0), "r"(b1));
}

// ---------------- edge index accessor (dtype-robust) ----------------
__device__ __forceinline__ int edge_at(const void* p, int i, int is64) {
    if (is64) return (int)((const long long*)p)[i];
    return ((const int*)p)[i];
}

// ---------------- fused init: zero counters + dtype detect ----------------
__global__ void k_init(const int* __restrict__ src_as_i32) {
    int i = blockIdx.x * 256 + threadIdx.x;
    if (i < NN) { g_deg_out[i] = 0; g_deg_in[i] = 0; g_cursor[i] = 0; }
    if (blockIdx.x == 0 && threadIdx.x == 0) {
        int allzero = 1;
        for (int j = 0; j < 256; j++)
            if (src_as_i32[2 * j + 1] != 0) { allzero = 0; break; }
        g_is64 = allzero;
    }
}

__global__ void k_degree(const void* __restrict__ src, const void* __restrict__ dst) {
    int e = blockIdx.x * 256 + threadIdx.x;
    if (e < NE) {
        int is64 = g_is64;
        unsigned s = (unsigned)edge_at(src, e, is64);
        unsigned d = (unsigned)edge_at(dst, e, is64);
        if (s < NN) atomicAdd(&g_deg_out[s], 1);
        if (d < NN) atomicAdd(&g_deg_in[d], 1);
    }
}

// ---------------- norm: WIDE kernel (rsqrt spread over the chip) ----------------
__global__ void k_norm() {
    int i = blockIdx.x * 256 + threadIdx.x;
    if (i < NN) {
        int a = g_deg_out[i]; if (a < 1) a = 1;
        int b = g_deg_in[i];  if (b < 1) b = 1;
        g_ns[i] = rsqrtf((float)a);
        g_nd[i] = rsqrtf((float)b);
    }
}

// ---------------- 3-phase parallel exclusive scan of deg_in -> rowptr ----------
// phase 1: per-block scan (49 blocks x 1024), local exclusive prefix + block sum
__global__ void k_scan1() {
    __shared__ int sh[1024];
    int tid = threadIdx.x;
    int i = blockIdx.x * 1024 + tid;
    int v = (i < NN) ? g_deg_in[i] : 0;
    sh[tid] = v;
    __syncthreads();
#pragma unroll
    for (int off = 1; off < 1024; off <<= 1) {
        int t = (tid >= off) ? sh[tid - off] : 0;
        __syncthreads();
        sh[tid] += t;
        __syncthreads();
    }
    if (i < NN) g_rowptr[i] = sh[tid] - v;   // local exclusive prefix
    if (tid == 1023) g_bsum[blockIdx.x] = sh[1023];
}

// phase 2: scan the 49 block sums (1 block, 64 threads)
__global__ void k_scan2() {
    __shared__ int sh[64];
    int t = threadIdx.x;
    int v = (t < NSB) ? g_bsum[t] : 0;
    sh[t] = v;
    __syncthreads();
#pragma unroll
    for (int off = 1; off < 64; off <<= 1) {
        int u = (t >= off) ? sh[t - off] : 0;
        __syncthreads();
        sh[t] += u;
        __syncthreads();
    }
    if (t < NSB) g_boff[t] = sh[t] - v;      // exclusive block offset
    if (t == NSB - 1) g_rowptr[NN] = sh[NSB - 1];  // total valid edges
}

// phase 3: add block offsets
__global__ void k_scan3() {
    int i = blockIdx.x * 1024 + threadIdx.x;
    if (i < NN) g_rowptr[i] += g_boff[blockIdx.x];
}

__global__ void k_csr(const void* __restrict__ src, const void* __restrict__ dst) {
    int e = blockIdx.x * 256 + threadIdx.x;
    if (e < NE) {
        int is64 = g_is64;
        unsigned s = (unsigned)edge_at(src, e, is64);
        unsigned d = (unsigned)edge_at(dst, e, is64);
        if (s < NN && d < NN) {
            int pos = atomicAdd(&g_cursor[d], 1);
            int slot = g_rowptr[d] + pos;
            if (slot < NE) g_csrc[slot] = (int)s;
        }
    }
}

// ---------------- fused pack: W1, W2 (single-term f16) and x -> f16 fragments ----
// b0: k = ks*16 + (lane&3)*2 (+1); b1: k += 8. n = nt8*8 + lane>>2.
__global__ void k_pack(const float* __restrict__ x,
                       const float* __restrict__ W1,
                       const float* __restrict__ W2) {
    int idx = blockIdx.x * 256 + threadIdx.x;
    if (idx < W1P + W2P) {
        const float* W = (idx < W1P) ? W1 : W2;
        uint2* out = (idx < W1P) ? g_B1p : g_B2p;
        int i = (idx < W1P) ? idx : idx - W1P;
        int Nt = (idx < W1P) ? 256 : 128;
        int NT8 = Nt >> 3;
        int lane = i & 31;
        int rest = i >> 5;               // ks*NT8 + nt8
        int nt8 = rest % NT8;
        int ks = rest / NT8;
        int k = ks * 16 + (lane & 3) * 2;
        int n = nt8 * 8 + (lane >> 2);
        uint2 o;
        o.x = packh(W[(size_t)k * Nt + n], W[(size_t)(k + 1) * Nt + n]);
        o.y = packh(W[(size_t)(k + 8) * Nt + n], W[(size_t)(k + 9) * Nt + n]);
        out[i] = o;
    } else {
        int i = idx - (W1P + W2P);
        if (i >= NN * 64) return;
        int r = i >> 6;
        int ks = (i >> 2) & 15;
        int q = i & 3;
        const float* ap = x + (size_t)r * 256 + ks * 16 + q * 2;
        float s = g_ns[r];
        float2 v0 = *(const float2*)ap;
        float2 v1 = *(const float2*)(ap + 8);
        uint2 o;
        o.x = packh(v0.x * s, v0.y * s);
        o.y = packh(v1.x * s, v1.y * s);
        g_A1p[i] = o;
    }
}

// ---------------- MMA GEMM: H[128 x Nt] (f16 out) = Apack @ Wf16 ----------------
// single-term weights: 1 MMA per (mt,j) per kstep.
template <bool L1>
__global__ void __launch_bounds__(256) k_mma() {
    constexpr int Nt = L1 ? 256 : 128;
    constexpr int NT8 = Nt >> 3;
    const uint2* Ap = L1 ? g_A1p : g_A2p;
    uint32_t* Ch = L1 ? (uint32_t*)g_H1h : (uint32_t*)g_H2h;
    const uint2* Bp = L1 ? g_B1p : g_B2p;

    int tid = threadIdx.x;
    int wid = tid >> 5, lid = tid & 31;
    int wm = wid >> 1, wn = wid & 1;
    int g = lid >> 2, q = lid & 3;
    int brow = blockIdx.x * 128;
    int bcol = blockIdx.y * 128;

    int rbase = brow + wm * 32 + g;
    int rows[4] = {rbase, rbase + 8, rbase + 16, rbase + 24};
    bool valid[4];
#pragma unroll
    for (int i = 0; i < 4; i++) valid[i] = rows[i] < NN;

    float acc[2][8][4];
#pragma unroll
    for (int mt = 0; mt < 2; mt++)
#pragma unroll
        for (int j = 0; j < 8; j++)
#pragma unroll
            for (int c = 0; c < 4; c++) acc[mt][j][c] = 0.f;

    const uint2* bbase = Bp + (size_t)((bcol >> 3) + wn * 8) * 32 + lid;

    for (int ks = 0; ks < 16; ks++) {
        // ---- A fragments: one 8B load per row per kstep ----
        uint32_t a[2][4];
#pragma unroll
        for (int ri = 0; ri < 4; ri++) {
            uint2 v = make_uint2(0u, 0u);
            if (valid[ri]) v = Ap[((size_t)rows[ri] * 16 + ks) * 4 + q];
            int mt = ri >> 1, half = ri & 1;
            a[mt][half] = v.x;
            a[mt][half + 2] = v.y;
        }
        // ---- B fragments: one 8B load per j ----
        const uint2* bk = bbase + (size_t)ks * NT8 * 32;
        uint2 b[8];
#pragma unroll
        for (int j = 0; j < 8; j++) b[j] = bk[j * 32];
        // ---- MMAs ----
#pragma unroll
        for (int mt = 0; mt < 2; mt++)
#pragma unroll
            for (int j = 0; j < 8; j++)
                mma_f16(acc[mt][j], a[mt], b[j].x, b[j].y);
    }

    // ---- epilogue: write f16 pairs ----
    int cb = bcol + wn * 64 + q * 2;
#pragma unroll
    for (int mt = 0; mt < 2; mt++) {
        int r0 = rows[mt * 2], r1 = rows[mt * 2 + 1];
#pragma unroll
        for (int j = 0; j < 8; j++) {
            int ci = (cb + j * 8) >> 1;
            if (valid[mt * 2])
                Ch[(size_t)r0 * (Nt / 2) + ci] = packh(acc[mt][j][0], acc[mt][j][1]);
            if (valid[mt * 2 + 1])
                Ch[(size_t)r1 * (Nt / 2) + ci] = packh(acc[mt][j][2], acc[mt][j][3]);
        }
    }
}

// ---------------- aggregation layer 1 (f16 gather, fp32 accum) ----------------
// emits layer-2 A directly in fragment-packed f16 form.
__global__ void k_agg1(const float* __restrict__ b1) {
    int node = blockIdx.x * 8 + threadIdx.y;
    if (node >= NN) return;
    int f = threadIdx.x;  // 0..31, cols 8f..8f+7
    int beg = g_rowptr[node], end = g_rowptr[node + 1];

    float acc[8];
#pragma unroll
    for (int i = 0; i < 8; i++) acc[i] = 0.f;

    int e = beg;
    for (; e + 4 <= end; e += 4) {
        uint4 v0 = g_H1h[(size_t)g_csrc[e] * 32 + f];
        uint4 v1 = g_H1h[(size_t)g_csrc[e + 1] * 32 + f];
        uint4 v2 = g_H1h[(size_t)g_csrc[e + 2] * 32 + f];
        uint4 v3 = g_H1h[(size_t)g_csrc[e + 3] * 32 + f];
#pragma unroll
        for (int w = 0; w < 4; w++) {
            uint32_t uu[4] = {v0.x, v0.y, v0.z, v0.w};
            uint32_t vv[4] = {v1.x, v1.y, v1.z, v1.w};
            uint32_t ww[4] = {v2.x, v2.y, v2.z, v2.w};
            uint32_t zz[4] = {v3.x, v3.y, v3.z, v3.w};
            float2 t0 = u2f2(uu[w]), t1 = u2f2(vv[w]), t2 = u2f2(ww[w]), t3 = u2f2(zz[w]);
            acc[2 * w] += (t0.x + t1.x) + (t2.x + t3.x);
            acc[2 * w + 1] += (t0.y + t1.y) + (t2.y + t3.y);
        }
    }
    for (; e < end; e++) {
        uint4 v = g_H1h[(size_t)g_csrc[e] * 32 + f];
        uint32_t uu[4] = {v.x, v.y, v.z, v.w};
#pragma unroll
        for (int w = 0; w < 4; w++) {
            float2 t = u2f2(uu[w]);
            acc[2 * w] += t.x;
            acc[2 * w + 1] += t.y;
        }
    }

    float nd = g_nd[node], ns = g_ns[node];
    float4 bb0 = ((const float4*)b1)[2 * f];
    float4 bb1 = ((const float4*)b1)[2 * f + 1];
    float bias[8] = {bb0.x, bb0.y, bb0.z, bb0.w, bb1.x, bb1.y, bb1.z, bb1.w};
    float r[8];
#pragma unroll
    for (int i = 0; i < 8; i++)
        r[i] = fmaxf(fmaf(acc[i], nd, bias[i]), 0.f) * ns;

    // packed write: pair i covers cols (8f+2i, 8f+2i+1); ks = f>>1, q = i, slot = f&1
    uint32_t* o = (uint32_t*)g_A2p;
    size_t base = (((size_t)node * 16 + (f >> 1)) * 4) * 2 + (f & 1);
#pragma unroll
    for (int i = 0; i < 4; i++)
        o[base + i * 2] = packh(r[2 * i], r[2 * i + 1]);
}

// ---------------- aggregation layer 2 (f16 gather, fp32 out) ----------------
__global__ void k_agg2(const float* __restrict__ b2, float* __restrict__ out) {
    int node = blockIdx.x * 8 + threadIdx.y;
    if (node >= NN) return;
    int f = threadIdx.x;  // 0..31, cols 4f..4f+3
    int beg = g_rowptr[node], end = g_rowptr[node + 1];

    float acc[4];
#pragma unroll
    for (int i = 0; i < 4; i++) acc[i] = 0.f;

    int e = beg;
    for (; e + 4 <= end; e += 4) {
        uint2 v0 = g_H2h[(size_t)g_csrc[e] * 32 + f];
        uint2 v1 = g_H2h[(size_t)g_csrc[e + 1] * 32 + f];
        uint2 v2 = g_H2h[(size_t)g_csrc[e + 2] * 32 + f];
        uint2 v3 = g_H2h[(size_t)g_csrc[e + 3] * 32 + f];
        float2 t0 = u2f2(v0.x), t1 = u2f2(v1.x), t2 = u2f2(v2.x), t3 = u2f2(v3.x);
        acc[0] += (t0.x + t1.x) + (t2.x + t3.x);
        acc[1] += (t0.y + t1.y) + (t2.y + t3.y);
        t0 = u2f2(v0.y); t1 = u2f2(v1.y); t2 = u2f2(v2.y); t3 = u2f2(v3.y);
        acc[2] += (t0.x + t1.x) + (t2.x + t3.x);
        acc[3] += (t0.y + t1.y) + (t2.y + t3.y);
    }
    for (; e < end; e++) {
        uint2 v = g_H2h[(size_t)g_csrc[e] * 32 + f];
        float2 t = u2f2(v.x);
        acc[0] += t.x; acc[1] += t.y;
        t = u2f2(v.y);
        acc[2] += t.x; acc[3] += t.y;
    }

    float nd = g_nd[node];
    float4 bb = ((const float4*)b2)[f];
    float4 r;
    r.x = fmaf(acc[0], nd, bb.x);
    r.y = fmaf(acc[1], nd, bb.y);
    r.z = fmaf(acc[2], nd, bb.z);
    r.w = fmaf(acc[3], nd, bb.w);
    ((float4*)out)[(size_t)node * 32 + f] = r;
}

// ---------------- launch ----------------
extern "C" void kernel_launch(void* const* d_in, const int* in_sizes, int n_in,
                              void* d_out, int out_size) {
    const float* x   = (const float*)d_in[0];
    const void*  src = d_in[1];
    const void*  dst = d_in[2];
    const float* W1  = (const float*)d_in[3];
    const float* b1  = (const float*)d_in[4];
    const float* W2  = (const float*)d_in[5];
    const float* b2  = (const float*)d_in[6];
    float* out = (float*)d_out;

    k_init<<<(NN + 255) / 256, 256>>>((const int*)src);
    k_degree<<<(NE + 255) / 256, 256>>>(src, dst);
    k_norm<<<(NN + 255) / 256, 256>>>();
    k_scan1<<<NSB, 1024>>>();
    k_scan2<<<1, 64>>>();
    k_scan3<<<NSB, 1024>>>();
    k_csr<<<(NE + 255) / 256, 256>>>(src, dst);
    k_pack<<<(W1P + W2P + NN * 64 + 255) / 256, 256>>>(x, W1, W2);

    const int GB = (NN + 127) / 128;  // 391
    k_mma<true><<<dim3(GB, 2), 256>>>();
    k_agg1<<<(NN + 7) / 8, dim3(32, 8)>>>(b1);
    k_mma<false><<<dim3(GB, 1), 256>>>();
    k_agg2<<<(NN + 7) / 8, dim3(32, 8)>>>(b2, out);
}

// round 16
// speedup vs baseline: 2.1222x; 1.0095x over previous
#include <cuda_runtime.h>
#include <cuda_fp16.h>
#include <cstdint>

#define NN 50000
#define NE 800000
#define NSB 49    // scan blocks: ceil(50000/1024)
#define GB 391    // mma row blocks: ceil(50000/128)

// ---------------- scratch (static device globals; no allocation) ----------------
__device__ int   g_deg_out[NN];
__device__ int   g_deg_in[NN];
__device__ float g_ns[NN];
__device__ float g_nd[NN];
__device__ int   g_rowptr[NN + 1];
__device__ int   g_cursor[NN];
__device__ int   g_csrc[NE];
__device__ int   g_is64;
__device__ int   g_bsum[NSB];
__device__ int   g_boff[NSB];

// fragment-packed f16 A operands (uint2 per (r,ks,q); index (r*16+ks)*4+q)
__device__ uint2 g_A1p[(size_t)NN * 64];    // layer1 A = f16(x), UNscaled
__device__ uint2 g_A2p[(size_t)NN * 64];    // layer2 A = relu(conv1)*ns (f16)

// f16 feature stores for aggregation gathers
__device__ uint4 g_H1h[(size_t)NN * 32];    // H1 = f16(x@W1), UNscaled
__device__ uint2 g_H2h[(size_t)NN * 32];    // H2p [NN,128] f16

// weight fragment packs (single-term f16): uint2{b0_pair, b1_pair},
// index (ks*NT8 + nt8)*32 + lane
__device__ uint2 g_B1p[16 * 32 * 32];       // W1: Nt=256
__device__ uint2 g_B2p[16 * 16 * 32];       // W2: Nt=128

#define W1P (16 * 32 * 32)                  // 16384
#define W2P (16 * 16 * 32)                  // 8192
#define PACKTOT (W1P + W2P + NN * 64)       // pack domain size

// ---------------- small helpers ----------------
__device__ __forceinline__ uint32_t h2u(__half2 h) {
    return *reinterpret_cast<uint32_t*>(&h);
}
__device__ __forceinline__ float2 u2f2(uint32_t u) {
    __half2 h = *reinterpret_cast<__half2*>(&u);
    return __half22float2(h);
}
__device__ __forceinline__ uint32_t packh(float f0, float f1) {
    return h2u(__floats2half2_rn(f0, f1));
}

__device__ __forceinline__ void mma_f16(float* c, const uint32_t* a, uint32_t b0, uint32_t b1) {
    asm volatile(
        "mma.sync.aligned.m16n8k16.row.col.f32.f16.f16.f32 "
        "{%0,%1,%2,%3}, {%4,%5,%6,%7}, {%8,%9}, {%0,%1,%2,%3};"
        : "+f"(c[0]), "+f"(c[1]), "+f"(c[2]), "+f"(c[3])
        : "r"(a[0]), "r"(a[1]), "r"(a[2]), "r"(a[3]), "r"(b0), "r"(b1));
}

__device__ __forceinline__ int edge_at(const void* p, int i, int is64) {
    if (is64) return (int)((const long long*)p)[i];
    return ((const int*)p)[i];
}

// ---------------- MMA body (register-only, fusion-safe: no smem/syncthreads) ----
template <bool L1>
__device__ __forceinline__ void mma_body(int bxr, int by, int tid) {
    constexpr int Nt = L1 ? 256 : 128;
    constexpr int NT8 = Nt >> 3;
    const uint2* Ap = L1 ? g_A1p : g_A2p;
    uint32_t* Ch = L1 ? (uint32_t*)g_H1h : (uint32_t*)g_H2h;
    const uint2* Bp = L1 ? g_B1p : g_B2p;

    int wid = tid >> 5, lid = tid & 31;
    int wm = wid >> 1, wn = wid & 1;
    int g = lid >> 2, q = lid & 3;
    int brow = bxr * 128;
    int bcol = by * 128;

    int rbase = brow + wm * 32 + g;
    int rows[4] = {rbase, rbase + 8, rbase + 16, rbase + 24};
    bool valid[4];
#pragma unroll
    for (int i = 0; i < 4; i++) valid[i] = rows[i] < NN;

    float acc[2][8][4];
#pragma unroll
    for (int mt = 0; mt < 2; mt++)
#pragma unroll
        for (int j = 0; j < 8; j++)
#pragma unroll
            for (int c = 0; c < 4; c++) acc[mt][j][c] = 0.f;

    const uint2* bbase = Bp + (size_t)((bcol >> 3) + wn * 8) * 32 + lid;

    for (int ks = 0; ks < 16; ks++) {
        uint32_t a[2][4];
#pragma unroll
        for (int ri = 0; ri < 4; ri++) {
            uint2 v = make_uint2(0u, 0u);
            if (valid[ri]) v = Ap[((size_t)rows[ri] * 16 + ks) * 4 + q];
            int mt = ri >> 1, half = ri & 1;
            a[mt][half] = v.x;
            a[mt][half + 2] = v.y;
        }
        const uint2* bk = bbase + (size_t)ks * NT8 * 32;
        uint2 b[8];
#pragma unroll
        for (int j = 0; j < 8; j++) b[j] = bk[j * 32];
#pragma unroll
        for (int mt = 0; mt < 2; mt++)
#pragma unroll
            for (int j = 0; j < 8; j++)
                mma_f16(acc[mt][j], a[mt], b[j].x, b[j].y);
    }

    int cb = bcol + wn * 64 + q * 2;
#pragma unroll
    for (int mt = 0; mt < 2; mt++) {
        int r0 = rows[mt * 2], r1 = rows[mt * 2 + 1];
#pragma unroll
        for (int j = 0; j < 8; j++) {
            int ci = (cb + j * 8) >> 1;
            if (valid[mt * 2])
                Ch[(size_t)r0 * (Nt / 2) + ci] = packh(acc[mt][j][0], acc[mt][j][1]);
            if (valid[mt * 2 + 1])
                Ch[(size_t)r1 * (Nt / 2) + ci] = packh(acc[mt][j][2], acc[mt][j][3]);
        }
    }
}

// ---------------- k_prep: init counters + dtype detect + full pack (no deps) -----
__global__ void k_prep(const float* __restrict__ x,
                       const float* __restrict__ W1,
                       const float* __restrict__ W2,
                       const int* __restrict__ src_as_i32) {
    int idx = blockIdx.x * 256 + threadIdx.x;
    if (idx == 0) {
        int allzero = 1;
        for (int j = 0; j < 256; j++)
            if (src_as_i32[2 * j + 1] != 0) { allzero = 0; break; }
        g_is64 = allzero;
    }
    if (idx < NN) { g_deg_out[idx] = 0; g_deg_in[idx] = 0; g_cursor[idx] = 0; }
    int p = idx - NN;
    if (p < 0 || p >= PACKTOT) return;
    if (p < W1P + W2P) {
        const float* W = (p < W1P) ? W1 : W2;
        uint2* out = (p < W1P) ? g_B1p : g_B2p;
        int i = (p < W1P) ? p : p - W1P;
        int Nt = (p < W1P) ? 256 : 128;
        int NT8 = Nt >> 3;
        int lane = i & 31;
        int rest = i >> 5;               // ks*NT8 + nt8
        int nt8 = rest % NT8;
        int ks = rest / NT8;
        int k = ks * 16 + (lane & 3) * 2;
        int n = nt8 * 8 + (lane >> 2);
        uint2 o;
        o.x = packh(W[(size_t)k * Nt + n], W[(size_t)(k + 1) * Nt + n]);
        o.y = packh(W[(size_t)(k + 8) * Nt + n], W[(size_t)(k + 9) * Nt + n]);
        out[i] = o;
    } else {
        int i = p - (W1P + W2P);
        int r = i >> 6;
        int ks = (i >> 2) & 15;
        int q = i & 3;
        const float* ap = x + (size_t)r * 256 + ks * 16 + q * 2;
        float2 v0 = *(const float2*)ap;
        float2 v1 = *(const float2*)(ap + 8);
        uint2 o;
        o.x = packh(v0.x, v0.y);
        o.y = packh(v1.x, v1.y);
        g_A1p[i] = o;
    }
}

// ---------------- k_work: fused mma1 (blocks [0,782)) + degree (rest) ------------
__global__ void __launch_bounds__(256) k_work(const void* __restrict__ src,
                                              const void* __restrict__ dst) {
    int bx = blockIdx.x;
    if (bx < 2 * GB) {
        mma_body<true>(bx >> 1, bx & 1, threadIdx.x);
    } else {
        int e = (bx - 2 * GB) * 256 + threadIdx.x;
        if (e < NE) {
            int is64 = g_is64;
            unsigned s = (unsigned)edge_at(src, e, is64);
            unsigned d = (unsigned)edge_at(dst, e, is64);
            if (s < NN) atomicAdd(&g_deg_out[s], 1);
            if (d < NN) atomicAdd(&g_deg_in[d], 1);
        }
    }
}

// ---------------- mma2 (layer 2) ----------------
__global__ void __launch_bounds__(256) k_mma2() {
    mma_body<false>(blockIdx.x, 0, threadIdx.x);
}

// ---------------- scan phase 1 + norm (fused; both read degree arrays) -----------
__global__ void k_scan1n() {
    __shared__ int sh[1024];
    int tid = threadIdx.x;
    int i = blockIdx.x * 1024 + tid;
    int v = 0;
    if (i < NN) {
        int a = g_deg_out[i]; if (a < 1) a = 1;
        int b = g_deg_in[i];
        g_ns[i] = rsqrtf((float)a);
        g_nd[i] = rsqrtf((float)(b < 1 ? 1 : b));
        v = b;
    }
    sh[tid] = v;
    __syncthreads();
#pragma unroll
    for (int off = 1; off < 1024; off <<= 1) {
        int t = (tid >= off) ? sh[tid - off] : 0;
        __syncthreads();
        sh[tid] += t;
        __syncthreads();
    }
    if (i < NN) g_rowptr[i] = sh[tid] - v;
    if (tid == 1023) g_bsum[blockIdx.x] = sh[1023];
}

__global__ void k_scan2() {
    __shared__ int sh[64];
    int t = threadIdx.x;
    int v = (t < NSB) ? g_bsum[t] : 0;
    sh[t] = v;
    __syncthreads();
#pragma unroll
    for (int off = 1; off < 64; off <<= 1) {
        int u = (t >= off) ? sh[t - off] : 0;
        __syncthreads();
        sh[t] += u;
        __syncthreads();
    }
    if (t < NSB) g_boff[t] = sh[t] - v;
    if (t == NSB - 1) g_rowptr[NN] = sh[NSB - 1];
}

__global__ void k_scan3() {
    int i = blockIdx.x * 1024 + threadIdx.x;
    if (i < NN) g_rowptr[i] += g_boff[blockIdx.x];
}

__global__ void k_csr(const void* __restrict__ src, const void* __restrict__ dst) {
    int e = blockIdx.x * 256 + threadIdx.x;
    if (e < NE) {
        int is64 = g_is64;
        unsigned s = (unsigned)edge_at(src, e, is64);
        unsigned d = (unsigned)edge_at(dst, e, is64);
        if (s < NN && d < NN) {
            int pos = atomicAdd(&g_cursor[d], 1);
            int slot = g_rowptr[d] + pos;
            if (slot < NE) g_csrc[slot] = (int)s;
        }
    }
}

// ---------------- aggregation layer 1: acc += ns[s] * H1[s] (per-edge scale) -----
__global__ void k_agg1(const float* __restrict__ b1) {
    int node = blockIdx.x * 8 + threadIdx.y;
    if (node >= NN) return;
    int f = threadIdx.x;  // 0..31, cols 8f..8f+7
    int beg = g_rowptr[node], end = g_rowptr[node + 1];

    float acc[8];
#pragma unroll
    for (int i = 0; i < 8; i++) acc[i] = 0.f;

    int e = beg;
    for (; e + 4 <= end; e += 4) {
        int s0 = g_csrc[e], s1 = g_csrc[e + 1], s2 = g_csrc[e + 2], s3 = g_csrc[e + 3];
        float n0 = g_ns[s0], n1 = g_ns[s1], n2 = g_ns[s2], n3 = g_ns[s3];
        uint4 v0 = g_H1h[(size_t)s0 * 32 + f];
        uint4 v1 = g_H1h[(size_t)s1 * 32 + f];
        uint4 v2 = g_H1h[(size_t)s2 * 32 + f];
        uint4 v3 = g_H1h[(size_t)s3 * 32 + f];
#pragma unroll
        for (int w = 0; w < 4; w++) {
            uint32_t uu[4] = {v0.x, v0.y, v0.z, v0.w};
            uint32_t vv[4] = {v1.x, v1.y, v1.z, v1.w};
            uint32_t ww[4] = {v2.x, v2.y, v2.z, v2.w};
            uint32_t zz[4] = {v3.x, v3.y, v3.z, v3.w};
            float2 t0 = u2f2(uu[w]), t1 = u2f2(vv[w]), t2 = u2f2(ww[w]), t3 = u2f2(zz[w]);
            acc[2 * w]     = fmaf(t0.x, n0, fmaf(t1.x, n1, fmaf(t2.x, n2, fmaf(t3.x, n3, acc[2 * w]))));
            acc[2 * w + 1] = fmaf(t0.y, n0, fmaf(t1.y, n1, fmaf(t2.y, n2, fmaf(t3.y, n3, acc[2 * w + 1]))));
        }
    }
    for (; e < end; e++) {
        int s = g_csrc[e];
        float n = g_ns[s];
        uint4 v = g_H1h[(size_t)s * 32 + f];
        uint32_t uu[4] = {v.x, v.y, v.z, v.w};
#pragma unroll
        for (int w = 0; w < 4; w++) {
            float2 t = u2f2(uu[w]);
            acc[2 * w]     = fmaf(t.x, n, acc[2 * w]);
            acc[2 * w + 1] = fmaf(t.y, n, acc[2 * w + 1]);
        }
    }

    float nd = g_nd[node], ns = g_ns[node];
    float4 bb0 = ((const float4*)b1)[2 * f];
    float4 bb1 = ((const float4*)b1)[2 * f + 1];
    float bias[8] = {bb0.x, bb0.y, bb0.z, bb0.w, bb1.x, bb1.y, bb1.z, bb1.w};
    float r[8];
#pragma unroll
    for (int i = 0; i < 8; i++)
        r[i] = fmaxf(fmaf(acc[i], nd, bias[i]), 0.f) * ns;

    // packed write: pair i covers cols (8f+2i, 8f+2i+1); ks = f>>1, q = i, slot = f&1
    uint32_t* o = (uint32_t*)g_A2p;
    size_t base = (((size_t)node * 16 + (f >> 1)) * 4) * 2 + (f & 1);
#pragma unroll
    for (int i = 0; i < 4; i++)
        o[base + i * 2] = packh(r[2 * i], r[2 * i + 1]);
}

// ---------------- aggregation layer 2 (f16 gather, fp32 out) ----------------
__global__ void k_agg2(const float* __restrict__ b2, float* __restrict__ out) {
    int node = blockIdx.x * 8 + threadIdx.y;
    if (node >= NN) return;
    int f = threadIdx.x;  // 0..31, cols 4f..4f+3
    int beg = g_rowptr[node], end = g_rowptr[node + 1];

    float acc[4];
#pragma unroll
    for (int i = 0; i < 4; i++) acc[i] = 0.f;

    int e = beg;
    for (; e + 4 <= end; e += 4) {
        uint2 v0 = g_H2h[(size_t)g_csrc[e] * 32 + f];
        uint2 v1 = g_H2h[(size_t)g_csrc[e + 1] * 32 + f];
        uint2 v2 = g_H2h[(size_t)g_csrc[e + 2] * 32 + f];
        uint2 v3 = g_H2h[(size_t)g_csrc[e + 3] * 32 + f];
        float2 t0 = u2f2(v0.x), t1 = u2f2(v1.x), t2 = u2f2(v2.x), t3 = u2f2(v3.x);
        acc[0] += (t0.x + t1.x) + (t2.x + t3.x);
        acc[1] += (t0.y + t1.y) + (t2.y + t3.y);
        t0 = u2f2(v0.y); t1 = u2f2(v1.y); t2 = u2f2(v2.y); t3 = u2f2(v3.y);
        acc[2] += (t0.x + t1.x) + (t2.x + t3.x);
        acc[3] += (t0.y + t1.y) + (t2.y + t3.y);
    }
    for (; e < end; e++) {
        uint2 v = g_H2h[(size_t)g_csrc[e] * 32 + f];
        float2 t = u2f2(v.x);
        acc[0] += t.x; acc[1] += t.y;
        t = u2f2(v.y);
        acc[2] += t.x; acc[3] += t.y;
    }

    float nd = g_nd[node];
    float4 bb = ((const float4*)b2)[f];
    float4 r;
    r.x = fmaf(acc[0], nd, bb.x);
    r.y = fmaf(acc[1], nd, bb.y);
    r.z = fmaf(acc[2], nd, bb.z);
    r.w = fmaf(acc[3], nd, bb.w);
    ((float4*)out)[(size_t)node * 32 + f] = r;
}

// ---------------- launch (single stream, 9 kernels) ----------------
extern "C" void kernel_launch(void* const* d_in, const int* in_sizes, int n_in,
                              void* d_out, int out_size) {
    const float* x   = (const float*)d_in[0];
    const void*  src = d_in[1];
    const void*  dst = d_in[2];
    const float* W1  = (const float*)d_in[3];
    const float* b1  = (const float*)d_in[4];
    const float* W2  = (const float*)d_in[5];
    const float* b2  = (const float*)d_in[6];
    float* out = (float*)d_out;

    k_prep<<<(NN + PACKTOT + 255) / 256, 256>>>(x, W1, W2, (const int*)src);
    k_work<<<2 * GB + (NE + 255) / 256, 256>>>(src, dst);   // mma1 ∥ degree
    k_scan1n<<<NSB, 1024>>>();
    k_scan2<<<1, 64>>>();
    k_scan3<<<NSB, 1024>>>();
    k_csr<<<(NE + 255) / 256, 256>>>(src, dst);
    k_agg1<<<(NN + 7) / 8, dim3(32, 8)>>>(b1);
    k_mma2<<<GB, 256>>>();
    k_agg2<<<(NN + 7) / 8, dim3(32, 8)>>>(b2, out);
}